// round 3
// baseline (speedup 1.0000x reference)
#include <cuda_runtime.h>

// Global double accumulator (allocation-free scratch).
__device__ double g_accum;

__global__ void k_init() {
    g_accum = 0.0;
}

__device__ __forceinline__ float giou_one(
    float px1, float py1, float px2, float py2, float pz1, float pz2,
    float tx1, float ty1, float tx2, float ty2, float tz1, float tz2)
{
    float vol1 = (px2 - px1) * (py2 - py1) * (pz2 - pz1);
    float vol2 = (tx2 - tx1) * (ty2 - ty1) * (tz2 - tz1);

    float ix = fmaxf(fminf(px2, tx2) - fmaxf(px1, tx1), 0.0f);
    float iy = fmaxf(fminf(py2, ty2) - fmaxf(py1, ty1), 0.0f);
    float iz = fmaxf(fminf(pz2, tz2) - fmaxf(pz1, tz1), 0.0f);
    float inter = ix * iy * iz;
    float uni   = vol1 + vol2 - inter;
    float iou   = inter / uni;

    float ex = fmaxf(fmaxf(px2, tx2) - fminf(px1, tx1), 0.0f);
    float ey = fmaxf(fmaxf(py2, ty2) - fminf(py1, ty1), 0.0f);
    float ez = fmaxf(fmaxf(pz2, tz2) - fminf(pz1, tz1), 0.0f);
    float enc = ex * ey * ez + 1e-7f;

    return iou - (enc - uni) / enc;
}

// Grid-stride over box-pairs: 3 float4 loads per input per pair, fully
// coalesced 16B accesses. Row layout: [x1,y1,x2,y2,z1,z2].
__global__ void __launch_bounds__(256) k_giou(
    const float4* __restrict__ p4, const float4* __restrict__ t4,
    int npairs, int nboxes)
{
    int stride = gridDim.x * blockDim.x;
    float s = 0.0f;

    for (int i = blockIdx.x * blockDim.x + threadIdx.x; i < npairs; i += stride) {
        float4 a0 = p4[3L * i + 0];
        float4 a1 = p4[3L * i + 1];
        float4 a2 = p4[3L * i + 2];
        float4 b0 = t4[3L * i + 0];
        float4 b1 = t4[3L * i + 1];
        float4 b2 = t4[3L * i + 2];

        s += giou_one(a0.x, a0.y, a0.z, a0.w, a1.x, a1.y,
                      b0.x, b0.y, b0.z, b0.w, b1.x, b1.y);
        s += giou_one(a1.z, a1.w, a2.x, a2.y, a2.z, a2.w,
                      b1.z, b1.w, b2.x, b2.y, b2.z, b2.w);
    }

    // odd tail box (not hit for N=4M, kept for generality)
    if ((nboxes & 1) && blockIdx.x == 0 && threadIdx.x == 0) {
        const float* pf = (const float*)p4;
        const float* tf = (const float*)t4;
        long b = (long)(nboxes - 1) * 6;
        s += giou_one(pf[b+0], pf[b+1], pf[b+2], pf[b+3], pf[b+4], pf[b+5],
                      tf[b+0], tf[b+1], tf[b+2], tf[b+3], tf[b+4], tf[b+5]);
    }

    // warp reduce
    #pragma unroll
    for (int o = 16; o > 0; o >>= 1)
        s += __shfl_down_sync(0xffffffffu, s, o);

    __shared__ float ws[8];
    int lane = threadIdx.x & 31;
    int w    = threadIdx.x >> 5;
    if (lane == 0) ws[w] = s;
    __syncthreads();

    if (w == 0) {
        s = (lane < 8) ? ws[lane] : 0.0f;
        #pragma unroll
        for (int o = 4; o > 0; o >>= 1)
            s += __shfl_down_sync(0xffffffffu, s, o);
        if (lane == 0)
            atomicAdd(&g_accum, (double)(-s));   // loss = -sum(giou)
    }
}

__global__ void k_final(float* __restrict__ out) {
    out[0] = (float)g_accum;
}

extern "C" void kernel_launch(void* const* d_in, const int* in_sizes, int n_in,
                              void* d_out, int out_size)
{
    const float* pred = (const float*)d_in[0];
    const float* targ = (const float*)d_in[1];
    float* out = (float*)d_out;

    int nboxes = in_sizes[0] / 6;
    int npairs = nboxes / 2;

    const int TPB = 256;
    int blocks = 148 * 8;                       // one full wave at occ=8
    int needed = (npairs + TPB - 1) / TPB;
    if (blocks > needed) blocks = needed;
    if (blocks < 1) blocks = 1;

    k_init<<<1, 1>>>();
    k_giou<<<blocks, TPB>>>((const float4*)pred, (const float4*)targ,
                            npairs, nboxes);
    k_final<<<1, 1>>>(out);
}

// round 4
// speedup vs baseline: 1.0069x; 1.0069x over previous
#include <cuda_runtime.h>

// Allocation-free scratch: per-block partials + completion ticket.
// g_count starts 0 (static init) and is reset to 0 by the last block each
// run, so every graph replay sees identical state -> deterministic.
#define MAX_BLOCKS 2048
__device__ double       g_part[MAX_BLOCKS];
__device__ unsigned int g_count = 0;

__device__ __forceinline__ float giou_one(
    float px1, float py1, float px2, float py2, float pz1, float pz2,
    float tx1, float ty1, float tx2, float ty2, float tz1, float tz2)
{
    float vol1 = (px2 - px1) * (py2 - py1) * (pz2 - pz1);
    float vol2 = (tx2 - tx1) * (ty2 - ty1) * (tz2 - tz1);

    float ix = fmaxf(fminf(px2, tx2) - fmaxf(px1, tx1), 0.0f);
    float iy = fmaxf(fminf(py2, ty2) - fmaxf(py1, ty1), 0.0f);
    float iz = fmaxf(fminf(pz2, tz2) - fmaxf(pz1, tz1), 0.0f);
    float inter = ix * iy * iz;
    float uni   = vol1 + vol2 - inter;
    float iou   = inter / uni;

    float ex = fmaxf(fmaxf(px2, tx2) - fminf(px1, tx1), 0.0f);
    float ey = fmaxf(fmaxf(py2, ty2) - fminf(py1, ty1), 0.0f);
    float ez = fmaxf(fmaxf(pz2, tz2) - fminf(pz1, tz1), 0.0f);
    float enc = ex * ey * ez + 1e-7f;

    return iou - (enc - uni) / enc;
}

// Single fused kernel: grid-stride GIoU + block reduce + last-block final
// reduction. 3 float4 loads per input per pair, fully coalesced.
// Row layout: [x1,y1,x2,y2,z1,z2].
__global__ void __launch_bounds__(256) k_giou(
    const float4* __restrict__ p4, const float4* __restrict__ t4,
    int npairs, int nboxes, float* __restrict__ out)
{
    int stride = gridDim.x * blockDim.x;
    float s = 0.0f;

    for (int i = blockIdx.x * blockDim.x + threadIdx.x; i < npairs; i += stride) {
        float4 a0 = p4[3L * i + 0];
        float4 a1 = p4[3L * i + 1];
        float4 a2 = p4[3L * i + 2];
        float4 b0 = t4[3L * i + 0];
        float4 b1 = t4[3L * i + 1];
        float4 b2 = t4[3L * i + 2];

        s += giou_one(a0.x, a0.y, a0.z, a0.w, a1.x, a1.y,
                      b0.x, b0.y, b0.z, b0.w, b1.x, b1.y);
        s += giou_one(a1.z, a1.w, a2.x, a2.y, a2.z, a2.w,
                      b1.z, b1.w, b2.x, b2.y, b2.z, b2.w);
    }

    // odd tail box (not hit for N=4M, kept for generality)
    if ((nboxes & 1) && blockIdx.x == 0 && threadIdx.x == 0) {
        const float* pf = (const float*)p4;
        const float* tf = (const float*)t4;
        long b = (long)(nboxes - 1) * 6;
        s += giou_one(pf[b+0], pf[b+1], pf[b+2], pf[b+3], pf[b+4], pf[b+5],
                      tf[b+0], tf[b+1], tf[b+2], tf[b+3], tf[b+4], tf[b+5]);
    }

    // ---- block reduce (float) ----
    #pragma unroll
    for (int o = 16; o > 0; o >>= 1)
        s += __shfl_down_sync(0xffffffffu, s, o);

    __shared__ float  ws[8];
    __shared__ bool   is_last;
    int lane = threadIdx.x & 31;
    int w    = threadIdx.x >> 5;
    if (lane == 0) ws[w] = s;
    __syncthreads();

    if (threadIdx.x == 0) {
        float bs = 0.0f;
        #pragma unroll
        for (int j = 0; j < 8; j++) bs += ws[j];
        g_part[blockIdx.x] = (double)bs;
        __threadfence();
        unsigned int t = atomicAdd(&g_count, 1u);
        is_last = (t == gridDim.x - 1);
    }
    __syncthreads();

    // ---- last block: final reduction over all partials ----
    if (is_last) {
        double d = 0.0;
        for (int j = threadIdx.x; j < gridDim.x; j += blockDim.x)
            d += g_part[j];

        #pragma unroll
        for (int o = 16; o > 0; o >>= 1)
            d += __shfl_down_sync(0xffffffffu, d, o);

        __shared__ double wd[8];
        if (lane == 0) wd[w] = d;
        __syncthreads();
        if (threadIdx.x == 0) {
            double tot = 0.0;
            #pragma unroll
            for (int j = 0; j < 8; j++) tot += wd[j];
            out[0] = (float)(-tot);   // loss = -sum(giou)
            g_count = 0;              // reset for next graph replay
        }
    }
}

extern "C" void kernel_launch(void* const* d_in, const int* in_sizes, int n_in,
                              void* d_out, int out_size)
{
    const float* pred = (const float*)d_in[0];
    const float* targ = (const float*)d_in[1];
    float* out = (float*)d_out;

    int nboxes = in_sizes[0] / 6;
    int npairs = nboxes / 2;

    const int TPB = 256;
    int blocks = 148 * 8;                       // one full wave at occ=8
    int needed = (npairs + TPB - 1) / TPB;
    if (blocks > needed) blocks = needed;
    if (blocks < 1) blocks = 1;
    if (blocks > MAX_BLOCKS) blocks = MAX_BLOCKS;

    k_giou<<<blocks, TPB>>>((const float4*)pred, (const float4*)targ,
                            npairs, nboxes, out);
}